// round 1
// baseline (speedup 1.0000x reference)
#include <cuda_runtime.h>

// Problem constants (fixed shapes from reference)
#define BATCH   128
#define TSTEPS  256
#define IN_F    256
#define OUT_F   256
#define M_TOTAL (BATCH * TSTEPS)   // 32768 rows

// Scratch for currents = spikes @ W + b  (33.5 MB)
__device__ float g_currents[(size_t)M_TOTAL * OUT_F];

// ---------------------------------------------------------------------------
// Kernel 1: fp32 SGEMM  C[M,256] = A[M,256] * W[256,256] + bias
// Classic 128x128x8 smem-tiled sgemm, 256 threads, 8x8 per-thread tile.
// Deliberately full fp32 (no tensor cores): spike threshold cur>0.5 makes the
// output extremely sensitive to GEMM rounding; this round calibrates headroom.
// ---------------------------------------------------------------------------
#define BM 128
#define BN 128
#define BK 8
#define TM 8
#define TN 8

__global__ void __launch_bounds__(256) sgemm_kernel(
    const float* __restrict__ A,
    const float* __restrict__ W,
    const float* __restrict__ bias,
    float* __restrict__ C)
{
    // As padded to 132 floats/row: kills the 2-way STS bank conflict from the
    // transpose store (128 floats = exact 4x bank wrap).
    __shared__ float As[BK][BM + 4];
    __shared__ float Bs[BK][BN];

    const int tid = threadIdx.x;
    const int bm  = blockIdx.y * BM;
    const int bn  = blockIdx.x * BN;

    const int tx = (tid & 15) * TN;   // col offset within tile
    const int ty = (tid >> 4) * TM;   // row offset within tile

    // A tile (128x8): one float4 per thread, transposed into As[k][m]
    const int a_row = tid >> 1;
    const int a_col = (tid & 1) << 2;
    // B tile (8x128): one float4 per thread, direct
    const int b_row = tid >> 5;
    const int b_col = (tid & 31) << 2;

    const float* Aptr = A + (size_t)(bm + a_row) * IN_F + a_col;
    const float* Wptr = W + (size_t)b_row * OUT_F + bn + b_col;

    float acc[TM][TN];
    #pragma unroll
    for (int i = 0; i < TM; i++)
        #pragma unroll
        for (int j = 0; j < TN; j++)
            acc[i][j] = 0.0f;

    for (int k0 = 0; k0 < IN_F; k0 += BK) {
        float4 av = *(const float4*)(Aptr + k0);
        float4 bv = *(const float4*)(Wptr + (size_t)k0 * OUT_F);

        As[a_col + 0][a_row] = av.x;
        As[a_col + 1][a_row] = av.y;
        As[a_col + 2][a_row] = av.z;
        As[a_col + 3][a_row] = av.w;
        *(float4*)&Bs[b_row][b_col] = bv;
        __syncthreads();

        #pragma unroll
        for (int k = 0; k < BK; k++) {
            float4 a0 = *(const float4*)&As[k][ty];
            float4 a1 = *(const float4*)&As[k][ty + 4];
            float4 b0 = *(const float4*)&Bs[k][tx];
            float4 b1 = *(const float4*)&Bs[k][tx + 4];
            float af[TM] = {a0.x, a0.y, a0.z, a0.w, a1.x, a1.y, a1.z, a1.w};
            float bf[TN] = {b0.x, b0.y, b0.z, b0.w, b1.x, b1.y, b1.z, b1.w};
            #pragma unroll
            for (int i = 0; i < TM; i++)
                #pragma unroll
                for (int j = 0; j < TN; j++)
                    acc[i][j] += af[i] * bf[j];
        }
        __syncthreads();
    }

    #pragma unroll
    for (int i = 0; i < TM; i++) {
        #pragma unroll
        for (int j = 0; j < TN; j += 4) {
            float4 o;
            o.x = acc[i][j + 0] + bias[bn + tx + j + 0];
            o.y = acc[i][j + 1] + bias[bn + tx + j + 1];
            o.z = acc[i][j + 2] + bias[bn + tx + j + 2];
            o.w = acc[i][j + 3] + bias[bn + tx + j + 3];
            *(float4*)&C[(size_t)(bm + ty + i) * OUT_F + bn + tx + j] = o;
        }
    }
}

// ---------------------------------------------------------------------------
// Kernel 2: LIF scan + spike + per-(b,t) LayerNorm over F=256.
// One block per batch row b, 256 threads (one per feature), sequential over t
// in chunks of 8 (one __syncthreads pair per 8 timesteps).
// s in {0,1}  =>  mean = popcount/256 (exact),  var = mu - mu^2 (exact algebra).
// ---------------------------------------------------------------------------
__global__ void __launch_bounds__(256) lif_scan_kernel(
    const float* __restrict__ cur,
    const float* __restrict__ gamma,   // ln_scale [T,F]
    const float* __restrict__ beta,    // ln_bias  [T,F]
    float* __restrict__ out)
{
    const int b    = blockIdx.x;
    const int f    = threadIdx.x;
    const int warp = f >> 5;
    const int lane = f & 31;

    __shared__ int s_cnt[8][8];   // [k within chunk][warp]

    // alpha = expf(-1/0.02) = expf(-50); (1 - alpha) rounds to exactly 1.0f
    const float ALPHA = 1.9287498479639178e-22f;

    const float* curb = cur + (size_t)b * (TSTEPS * OUT_F);
    float*       outb = out + (size_t)b * (TSTEPS * OUT_F);

    float v = 0.0f;

    for (int t0 = 0; t0 < TSTEPS; t0 += 8) {
        float sarr[8];
        #pragma unroll
        for (int k = 0; k < 8; k++) {
            float c = curb[(size_t)(t0 + k) * OUT_F + f];
            v = ALPHA * v + c;               // (1-alpha)*c == c in fp32
            bool sp = (v - 0.5f) > 0.0f;     // spike_surrogate forward: Heaviside
            sarr[k] = sp ? 1.0f : 0.0f;
            if (sp) v = 0.0f;                // RESET = 0
            unsigned m = __ballot_sync(0xffffffffu, sp);
            if (lane == 0) s_cnt[k][warp] = __popc(m);
        }
        __syncthreads();

        #pragma unroll
        for (int k = 0; k < 8; k++) {
            int tot = s_cnt[k][0] + s_cnt[k][1] + s_cnt[k][2] + s_cnt[k][3]
                    + s_cnt[k][4] + s_cnt[k][5] + s_cnt[k][6] + s_cnt[k][7];
            float mu   = (float)tot * (1.0f / 256.0f);   // exact
            float var  = mu - mu * mu;                   // s in {0,1}: E[s^2]=E[s]
            float rstd = rsqrtf(var + 1e-6f);
            const int t = t0 + k;
            float g  = gamma[(size_t)t * OUT_F + f];
            float be = beta [(size_t)t * OUT_F + f];
            outb[(size_t)t * OUT_F + f] = (sarr[k] - mu) * rstd * g + be;
        }
        __syncthreads();
    }
}

// ---------------------------------------------------------------------------
// Launch
// Inputs (metadata order): spikes[B,T,IN_F] f32, W[IN_F,F] f32, b[F] f32,
//                          ln_scale[T,F] f32, ln_bias[T,F] f32
// Output: [B,T,F] f32
// ---------------------------------------------------------------------------
extern "C" void kernel_launch(void* const* d_in, const int* in_sizes, int n_in,
                              void* d_out, int out_size)
{
    const float* spikes   = (const float*)d_in[0];
    const float* W        = (const float*)d_in[1];
    const float* bvec     = (const float*)d_in[2];
    const float* ln_scale = (const float*)d_in[3];
    const float* ln_bias  = (const float*)d_in[4];
    float* out = (float*)d_out;

    float* cur = nullptr;
    cudaGetSymbolAddress((void**)&cur, g_currents);

    dim3 ggrid(OUT_F / BN, M_TOTAL / BM);   // (2, 256)
    sgemm_kernel<<<ggrid, 256>>>(spikes, W, bvec, cur);
    lif_scan_kernel<<<BATCH, 256>>>(cur, ln_scale, ln_bias, out);
}

// round 12
// speedup vs baseline: 2.0951x; 2.0951x over previous
#include <cuda_runtime.h>
#include <cuda_fp16.h>
#include <mma.h>
#include <cstdint>

using namespace nvcuda;

// ---------------------------------------------------------------------------
// out[b,t,f] = LayerNorm_f( spike( LIF(spikes@W + b) ) )
// alpha=exp(-50): recurrence degenerates (R1-validated, rel_err 4e-8):
//   s[row,f] = ((spikes@W)[row,f] + b[f] > 0.5)
// WMMA fp16 2-split GEMM (Ah*Wh + Ah*Wl + Al*Wh, fp32 accum) + guarded fp32
// recompute + exact {0,1}-LayerNorm.
// ALL kernels use static __shared__ <= 47KB: no cudaFuncSetAttribute, no
// dynamic smem (R8/R10 identical rel_err 0.9787 => main kernel never launched;
// prime suspect was the >48KB dynamic-smem opt-in).
// ---------------------------------------------------------------------------

#define TSTEPS  256
#define IN_F    256
#define OUT_F   256
#define M_TOTAL 32768

__device__ __half   g_wt_hi[OUT_F * IN_F];   // W^T hi, [f][k]
__device__ __half   g_wt_lo[OUT_F * IN_F];   // W^T lo, [f][k]
__device__ uint32_t g_sbits[M_TOTAL * 8];    // spike bits, [row][8 words]

// ======================= Kernel 0: W^T + fp16 split ========================
__global__ void __launch_bounds__(256) prep_wt(const float* __restrict__ W) {
    __shared__ float tile[32][33];
    const int tx  = threadIdx.x & 31;
    const int ty0 = threadIdx.x >> 5;
    const int bi = blockIdx.y, bj = blockIdx.x;
    #pragma unroll
    for (int p = 0; p < 4; p++) {
        int ty = ty0 + p * 8;
        tile[ty][tx] = W[(bi * 32 + ty) * OUT_F + bj * 32 + tx];
    }
    __syncthreads();
    #pragma unroll
    for (int p = 0; p < 4; p++) {
        int ty = ty0 + p * 8;
        int f = bj * 32 + ty, i = bi * 32 + tx;
        float v = tile[tx][ty];
        __half h = __float2half_rn(v);
        __half l = __float2half_rn(v - __half2float(h));
        g_wt_hi[f * IN_F + i] = h;
        g_wt_lo[f * IN_F + i] = l;
    }
}

// ================= Kernel 1: GEMM + spike bits (static smem) ===============
// Grid 512 = 256 row-groups x 2 col-halves. 256 thr = 8 warps (2m x 4n).
// CTA tile 128 rows x 128 cols; warp tile 64x32 = 4x2 wmma tiles.
// Virtual K=768 in 12 chunks of 64: c0-3 Ah*Wh, c4-7 Ah*Wl, c8-11 Al*Wh.
__global__ void __launch_bounds__(256) gemm_spike(
    const float* __restrict__ spikes,   // [M_TOTAL, IN_F]
    const float* __restrict__ W,        // fp32, for borderline recompute
    const float* __restrict__ bvec)     // [OUT_F]
{
    __shared__ __half   As[128][72];    // 18432 B (stride 144B: conflict-free)
    __shared__ __half   Bs[128][72];    // 18432 B
    __shared__ float    Cw[8][256];     //  8192 B (per-warp 16x16 C scratch)
    __shared__ uint32_t sb[128][4];     //  2048 B  -> total 47104 B

    const int tid    = threadIdx.x;
    const int lane   = tid & 31;
    const int wid    = tid >> 5;
    const int warp_m = wid >> 2;        // 0..1
    const int warp_n = wid & 3;         // 0..3
    const int rowgrp = blockIdx.x >> 1;
    const int half   = blockIdx.x & 1;
    const int base_row = rowgrp * 128;
    const int base_col = half * 128;

    ((uint32_t*)sb)[tid] = 0;
    ((uint32_t*)sb)[tid + 256] = 0;

    wmma::fragment<wmma::accumulator, 16, 16, 16, float> acc[4][2];
    #pragma unroll
    for (int mt = 0; mt < 4; mt++) {
        wmma::fill_fragment(acc[mt][0], 0.0f);
        wmma::fill_fragment(acc[mt][1], 0.0f);
    }

    for (int c = 0; c < 12; c++) {
        const int  kbase = (c & 3) * 64;
        const bool alo   = (c >= 8);

        // ---- stage A slice: 128 rows x 64 halves (convert fp32 -> hi/lo)
        #pragma unroll
        for (int it = 0; it < 8; it++) {
            int u = it * 256 + tid;            // 2048 float4
            int row = u >> 4, kq = u & 15;
            float4 v = ((const float4*)spikes)[(size_t)(base_row + row) * 64
                                               + (kbase >> 2) + kq];
            __half h0 = __float2half_rn(v.x), h1 = __float2half_rn(v.y);
            __half h2 = __float2half_rn(v.z), h3 = __float2half_rn(v.w);
            if (alo) {
                h0 = __float2half_rn(v.x - __half2float(h0));
                h1 = __float2half_rn(v.y - __half2float(h1));
                h2 = __float2half_rn(v.z - __half2float(h2));
                h3 = __float2half_rn(v.w - __half2float(h3));
            }
            __half2 p01 = __halves2half2(h0, h1), p23 = __halves2half2(h2, h3);
            uint2 pk;
            pk.x = *(uint32_t*)&p01; pk.y = *(uint32_t*)&p23;
            *(uint2*)&As[row][kq * 4] = pk;
        }
        // ---- stage B slice: 128 f-rows x 64 halves from W^T part
        {
            const __half* wsrc = (c < 4) ? g_wt_hi : (c < 8) ? g_wt_lo : g_wt_hi;
            const uint4* Bg = (const uint4*)wsrc;     // 32 uint4 per f-row
            #pragma unroll
            for (int it = 0; it < 4; it++) {
                int u = it * 256 + tid;        // 1024 uint4
                int n = u >> 3, q = u & 7;
                uint4 v = Bg[(size_t)(base_col + n) * 32 + (kbase >> 3) + q];
                *(uint4*)&Bs[n][q * 8] = v;
            }
        }
        __syncthreads();

        // ---- WMMA over this 64-k chunk (4 k-steps of 16)
        #pragma unroll
        for (int ks = 0; ks < 4; ks++) {
            wmma::fragment<wmma::matrix_b, 16, 16, 16, __half, wmma::col_major> b[2];
            wmma::load_matrix_sync(b[0], &Bs[warp_n * 32][ks * 16], 72);
            wmma::load_matrix_sync(b[1], &Bs[warp_n * 32 + 16][ks * 16], 72);
            #pragma unroll
            for (int mt = 0; mt < 4; mt++) {
                wmma::fragment<wmma::matrix_a, 16, 16, 16, __half, wmma::row_major> a;
                wmma::load_matrix_sync(a, &As[warp_m * 64 + mt * 16][ks * 16], 72);
                wmma::mma_sync(acc[mt][0], a, b[0], acc[mt][0]);
                wmma::mma_sync(acc[mt][1], a, b[1], acc[mt][1]);
            }
        }
        __syncthreads();
    }

    // ---- Epilogue: bias + threshold (+exact recompute) -> bit pack
    const int r  = lane >> 1;           // 0..15 tile row
    const int c8 = (lane & 1) * 8;      // col-half within tile

    #pragma unroll
    for (int mt = 0; mt < 4; mt++) {
        #pragma unroll
        for (int nt = 0; nt < 2; nt++) {
            wmma::store_matrix_sync(&Cw[wid][0], acc[mt][nt], 16,
                                    wmma::mem_row_major);
            __syncwarp();
            int lrow   = warp_m * 64 + mt * 16 + r;
            int colloc = warp_n * 32 + nt * 16 + c8;    // 0..127 within half
            int colg   = base_col + colloc;
            uint32_t bits = 0;
            #pragma unroll
            for (int i = 0; i < 8; i++) {
                float cur = Cw[wid][r * 16 + c8 + i] + bvec[colg + i];
                float cmp = cur - 0.5f;
                if (fabsf(cmp) < 1e-4f) {
                    // exact fp32 sequential-k recompute (matches ref ~1e-8)
                    int grow = base_row + lrow;
                    const float* sr = spikes + (size_t)grow * IN_F;
                    float a2 = 0.0f;
                    for (int kk = 0; kk < IN_F; kk++)
                        a2 = fmaf(sr[kk], W[(size_t)kk * OUT_F + colg + i], a2);
                    cmp = (a2 + bvec[colg + i]) - 0.5f;
                }
                if (cmp > 0.0f) bits |= 1u << i;
            }
            atomicOr(&sb[lrow][colloc >> 5], bits << (colloc & 31));
            __syncwarp();
        }
    }
    __syncthreads();

    // ---- flush bits to global: [row][8 words], this CTA owns words half*4..+3
    #pragma unroll
    for (int it = 0; it < 2; it++) {
        int u = it * 256 + tid;            // 512 words
        int row = u >> 2, w = u & 3;
        g_sbits[(size_t)(base_row + row) * 8 + half * 4 + w] = sb[row][w];
    }
}

// ================= Kernel 2: exact {0,1}-LayerNorm + store =================
// Grid 256, 256 thr; block handles 128 rows. mu = popc/256 (exact),
// var = mu - mu^2 (exact for {0,1}).
__global__ void __launch_bounds__(256) ln_kernel(
    const float* __restrict__ gamma,    // [T, F]
    const float* __restrict__ beta,     // [T, F]
    float* __restrict__ out)            // [M_TOTAL, OUT_F]
{
    __shared__ uint32_t bits_s[128][8];
    __shared__ float2   stats[128];
    const int tid = threadIdx.x;
    const int base_row = blockIdx.x * 128;

    #pragma unroll
    for (int it = 0; it < 4; it++) {
        int u = it * 256 + tid;            // 1024 words
        ((uint32_t*)bits_s)[u] = g_sbits[(size_t)base_row * 8 + u];
    }
    __syncthreads();

    if (tid < 128) {
        int cnt = 0;
        #pragma unroll
        for (int w = 0; w < 8; w++) cnt += __popc(bits_s[tid][w]);
        float mu = (float)cnt * (1.0f / 256.0f);
        stats[tid] = make_float2(mu, rsqrtf(mu - mu * mu + 1e-6f));
    }
    __syncthreads();

    const int fo = tid;                     // one feature per thread
    const uint32_t wsel = fo >> 5, bsel = fo & 31;
    for (int row = 0; row < 128; row++) {
        float s = (float)((bits_s[row][wsel] >> bsel) & 1u);
        float2 st = stats[row];
        int grow = base_row + row;
        int t = grow & (TSTEPS - 1);
        out[(size_t)grow * OUT_F + fo] =
            (s - st.x) * st.y * gamma[(size_t)t * OUT_F + fo]
            + beta[(size_t)t * OUT_F + fo];
    }
}

// =============================== Launch ====================================
extern "C" void kernel_launch(void* const* d_in, const int* in_sizes, int n_in,
                              void* d_out, int out_size)
{
    const float* spikes   = (const float*)d_in[0];
    const float* W        = (const float*)d_in[1];
    const float* bvec     = (const float*)d_in[2];
    const float* ln_scale = (const float*)d_in[3];
    const float* ln_bias  = (const float*)d_in[4];
    float* out = (float*)d_out;

    prep_wt<<<dim3(8, 8), 256>>>(W);
    gemm_spike<<<512, 256>>>(spikes, W, bvec);
    ln_kernel<<<256, 256>>>(ln_scale, ln_bias, out);
}